// round 1
// baseline (speedup 1.0000x reference)
#include <cuda_runtime.h>

#define L_LAYERS 6
#define DIMV     40
#define HV       128
#define ADIMV    20
#define DINV     276
#define BTOT     131072
#define MTILE    128
#define NTHR     256
#define H0STR    132      // padded h stride (132 % 32 == 4 -> conflict-free A frag loads)
#define ZASTR    28       // 28 % 32 == 28 (== -4) -> conflict-free A frag loads
#define ASSTR    36       // 36 % 32 == 4
#define ZROWSTR  41

// smem layout (floats)
#define OFF_A   0
#define OFF_W   (OFF_A + 128*ASSTR)        // 4608
#define OFF_H0  (OFF_W + 32*HV)            // 8704
#define OFF_H1  (OFF_H0 + 128*H0STR)       // 25600
#define OFF_ZA  (OFF_H1 + 128*H0STR)       // 42496
#define OFF_ZB  (OFF_ZA + 128*ZASTR)       // 46080
#define OFF_ST  (OFF_ZB + 128*ADIMV)       // 48640
#define OFF_END (OFF_ST + 128*DIMV)        // 53760
#define SMEM_BYTES (OFF_END*4 + 4*ADIMV*4)

__device__ float g_z[(size_t)BTOT * DIMV];
__device__ float g_ld[BTOT];

__device__ __forceinline__ unsigned f2tf(float x) {
    unsigned r;
    asm("cvt.rna.tf32.f32 %0, %1;" : "=r"(r) : "f"(x));
    return r;
}

__device__ __forceinline__ void mma8(float c[4], const unsigned a[4], const unsigned b[2]) {
    asm volatile(
        "mma.sync.aligned.m16n8k8.row.col.f32.tf32.tf32.f32 "
        "{%0,%1,%2,%3}, {%4,%5,%6,%7}, {%8,%9}, {%0,%1,%2,%3};\n"
        : "+f"(c[0]), "+f"(c[1]), "+f"(c[2]), "+f"(c[3])
        : "r"(a[0]), "r"(a[1]), "r"(a[2]), "r"(a[3]), "r"(b[0]), "r"(b[1]));
}

// split-load one A fragment (4 elems) into hi/lo tf32 parts
__device__ __forceinline__ void load_a_frag(const float* Ab, int astr, int r0, int c,
                                            unsigned ah[4], unsigned al[4]) {
    float v0 = Ab[r0 * astr + c];
    float v1 = Ab[(r0 + 8) * astr + c];
    float v2 = Ab[r0 * astr + c + 4];
    float v3 = Ab[(r0 + 8) * astr + c + 4];
    ah[0] = f2tf(v0); al[0] = f2tf(v0 - __uint_as_float(ah[0]));
    ah[1] = f2tf(v1); al[1] = f2tf(v1 - __uint_as_float(ah[1]));
    ah[2] = f2tf(v2); al[2] = f2tf(v2 - __uint_as_float(ah[2]));
    ah[3] = f2tf(v3); al[3] = f2tf(v3 - __uint_as_float(ah[3]));
}

// main-GEMM chunk: N=128, warps as 4(m) x 2(n); each warp 32 rows x 64 cols
template <int NKS>
__device__ __forceinline__ void mma_block(float acc[2][8][4], const float* __restrict__ Ab,
                                          int astr, int ak0, const float* __restrict__ Wb,
                                          int wm, int wn, int g, int t4) {
#pragma unroll
    for (int ks = 0; ks < NKS; ks++) {
        unsigned ah[2][4], al[2][4];
#pragma unroll
        for (int mt = 0; mt < 2; mt++) {
            int r0 = wm * 32 + mt * 16 + g;
            int c = ak0 + ks * 8 + t4;
            load_a_frag(Ab, astr, r0, c, ah[mt], al[mt]);
        }
#pragma unroll
        for (int nt = 0; nt < 8; nt++) {
            int col = wn * 64 + nt * 8 + g;
            unsigned b[2];
            b[0] = f2tf(Wb[(ks * 8 + t4) * HV + col]);
            b[1] = f2tf(Wb[(ks * 8 + t4 + 4) * HV + col]);
#pragma unroll
            for (int mt = 0; mt < 2; mt++) {
                mma8(acc[mt][nt], ah[mt], b);
                mma8(acc[mt][nt], al[mt], b);
            }
        }
    }
}

// GEMM4 chunk: N=40, warps as 8(m) x 1(n); each warp 16 rows x 40 cols
__device__ __forceinline__ void mma_block4(float a4[5][4], const float* __restrict__ Ab,
                                           int astr, int ak0, const float* __restrict__ Wb,
                                           int warp, int g, int t4) {
#pragma unroll
    for (int ks = 0; ks < 4; ks++) {
        unsigned ah[4], al[4];
        int r0 = warp * 16 + g;
        int c = ak0 + ks * 8 + t4;
        load_a_frag(Ab, astr, r0, c, ah, al);
#pragma unroll
        for (int nt = 0; nt < 5; nt++) {
            unsigned b[2];
            b[0] = f2tf(Wb[(ks * 8 + t4) * HV + nt * 8 + g]);
            b[1] = f2tf(Wb[(ks * 8 + t4 + 4) * HV + nt * 8 + g]);
            mma8(a4[nt], ah, b);
            mma8(a4[nt], al, b);
        }
    }
}

__device__ __forceinline__ void epilogue_silu(float acc[2][8][4], const float* __restrict__ bias,
                                              float* __restrict__ hdst, int wm, int wn, int g, int t4) {
#pragma unroll
    for (int mt = 0; mt < 2; mt++)
#pragma unroll
        for (int nt = 0; nt < 8; nt++)
#pragma unroll
            for (int e = 0; e < 4; e++) {
                int row = wm * 32 + mt * 16 + g + ((e >= 2) ? 8 : 0);
                int col = wn * 64 + nt * 8 + t4 * 2 + (e & 1);
                float v = acc[mt][nt][e] + bias[col];
                v = v / (1.0f + __expf(-v));
                hdst[row * H0STR + col] = v;
            }
}

__device__ __forceinline__ void zero_acc(float acc[2][8][4]) {
#pragma unroll
    for (int mt = 0; mt < 2; mt++)
#pragma unroll
        for (int nt = 0; nt < 8; nt++)
#pragma unroll
            for (int e = 0; e < 4; e++) acc[mt][nt][e] = 0.0f;
}

__global__ void __launch_bounds__(NTHR, 1)
flow_layer_kernel(const float* __restrict__ xin, float* __restrict__ zfinal,
                  float* __restrict__ ldfinal,
                  const float* __restrict__ ctx, const float* __restrict__ te,
                  const float* __restrict__ W1, const float* __restrict__ b1,
                  const float* __restrict__ W2, const float* __restrict__ b2,
                  const float* __restrict__ W3, const float* __restrict__ b3,
                  const float* __restrict__ Wsw, const float* __restrict__ bsw,
                  const float* __restrict__ Wtw, const float* __restrict__ btw,
                  const int* __restrict__ perm, const int* __restrict__ idxa,
                  const int* __restrict__ idxb, int layer) {
    const int tid = threadIdx.x;
    const int warp = tid >> 5, lane = tid & 31;
    const int g = lane >> 2, t4 = lane & 3;
    const int wm = warp >> 1, wn = warp & 1;
    const int rb = blockIdx.x * MTILE;
    const bool first = (layer == 0), last = (layer == L_LAYERS - 1);
    const float* zin = first ? xin : g_z;
    float* zout = last ? zfinal : g_z;

    extern __shared__ float sm[];
    float* A_s = sm + OFF_A;
    float* W_s = sm + OFF_W;
    float* h0  = sm + OFF_H0;
    float* h1  = sm + OFF_H1;
    float* za  = sm + OFF_ZA;
    float* zb  = sm + OFF_ZB;
    float* st  = sm + OFF_ST;
    int* sia = (int*)(sm + OFF_END);
    int* sib = sia + ADIMV;
    int* sga = sib + ADIMV;
    int* sgb = sga + ADIMV;

    // composed gather / scatter indices
    if (tid < ADIMV) {
        int v = idxa[layer * ADIMV + tid];
        sia[tid] = v;
        sga[tid] = perm[layer * DIMV + v];
    } else if (tid < 2 * ADIMV) {
        int k = tid - ADIMV;
        int v = idxb[layer * ADIMV + k];
        sib[k] = v;
        sgb[k] = perm[layer * DIMV + v];
    }
    // coalesced load of z rows into h1 scratch
    for (int i = tid; i < MTILE * DIMV; i += NTHR) {
        int r = i / DIMV, c = i - r * DIMV;
        h1[r * ZROWSTR + c] = zin[(size_t)(rb + r) * DIMV + c];
    }
    __syncthreads();
    // gather permuted halves
    for (int i = tid; i < MTILE * ADIMV; i += NTHR) {
        int r = i / ADIMV, k = i - r * ADIMV;
        za[r * ZASTR + k] = h1[r * ZROWSTR + sga[k]];
        zb[r * ADIMV + k] = h1[r * ZROWSTR + sgb[k]];
    }
    for (int i = tid; i < MTILE * 8; i += NTHR) {
        int r = i >> 3, c = i & 7;
        za[r * ZASTR + ADIMV + c] = 0.0f;  // pad k 20..27 with zeros
    }
    __syncthreads();

    float acc[2][8][4];
    zero_acc(acc);

    const float* W1l = W1 + (size_t)layer * DINV * HV;

    // ---- GEMM1: [za | ctx | te] @ W1  (K = 24(pad) + 128 + 128) ----
    // segment z_a: W1 rows 0..19, padded to 24
    for (int i = tid; i < 24 * HV; i += NTHR) {
        int r = i >> 7;
        W_s[i] = (r < ADIMV) ? W1l[i] : 0.0f;
    }
    __syncthreads();
    mma_block<3>(acc, za, ZASTR, 0, W_s, wm, wn, g, t4);

    // segment ctx: W1 rows 20..147
    for (int kc = 0; kc < 4; kc++) {
        __syncthreads();
        for (int i = tid; i < MTILE * 32; i += NTHR) {
            int r = i >> 5, c = i & 31;
            A_s[r * ASSTR + c] = ctx[(size_t)(rb + r) * HV + kc * 32 + c];
        }
        for (int i = tid; i < 32 * HV; i += NTHR)
            W_s[i] = W1l[(ADIMV + kc * 32) * HV + i];
        __syncthreads();
        mma_block<4>(acc, A_s, ASSTR, 0, W_s, wm, wn, g, t4);
    }
    // segment te: W1 rows 148..275
    for (int kc = 0; kc < 4; kc++) {
        __syncthreads();
        for (int i = tid; i < MTILE * 32; i += NTHR) {
            int r = i >> 5, c = i & 31;
            A_s[r * ASSTR + c] = te[(size_t)(rb + r) * HV + kc * 32 + c];
        }
        for (int i = tid; i < 32 * HV; i += NTHR)
            W_s[i] = W1l[(ADIMV + 128 + kc * 32) * HV + i];
        __syncthreads();
        mma_block<4>(acc, A_s, ASSTR, 0, W_s, wm, wn, g, t4);
    }
    epilogue_silu(acc, b1 + layer * HV, h0, wm, wn, g, t4);

    // ---- GEMM2: h0 @ W2 -> h1 ----
    zero_acc(acc);
    const float* W2l = W2 + (size_t)layer * HV * HV;
    for (int kc = 0; kc < 4; kc++) {
        __syncthreads();
        for (int i = tid; i < 32 * HV; i += NTHR)
            W_s[i] = W2l[kc * 32 * HV + i];
        __syncthreads();
        mma_block<4>(acc, h0, H0STR, kc * 32, W_s, wm, wn, g, t4);
    }
    epilogue_silu(acc, b2 + layer * HV, h1, wm, wn, g, t4);

    // ---- GEMM3: h1 @ W3 -> h0 ----
    zero_acc(acc);
    const float* W3l = W3 + (size_t)layer * HV * HV;
    for (int kc = 0; kc < 4; kc++) {
        __syncthreads();
        for (int i = tid; i < 32 * HV; i += NTHR)
            W_s[i] = W3l[kc * 32 * HV + i];
        __syncthreads();
        mma_block<4>(acc, h1, H0STR, kc * 32, W_s, wm, wn, g, t4);
    }
    epilogue_silu(acc, b3 + layer * HV, h0, wm, wn, g, t4);

    // ---- GEMM4: h0 @ [Ws | Wt] (N = 40) -> st ----
    float a4[5][4];
#pragma unroll
    for (int nt = 0; nt < 5; nt++)
#pragma unroll
        for (int e = 0; e < 4; e++) a4[nt][e] = 0.0f;
    const float* Wsl = Wsw + (size_t)layer * HV * ADIMV;
    const float* Wtl = Wtw + (size_t)layer * HV * ADIMV;
    for (int kc = 0; kc < 4; kc++) {
        __syncthreads();
        for (int i = tid; i < 32 * DIMV; i += NTHR) {
            int r = i / DIMV, c = i - r * DIMV;
            int k = kc * 32 + r;
            W_s[r * HV + c] = (c < ADIMV) ? Wsl[k * ADIMV + c]
                                          : Wtl[k * ADIMV + (c - ADIMV)];
        }
        __syncthreads();
        mma_block4(a4, h0, H0STR, kc * 32, W_s, warp, g, t4);
    }
    // epilogue 4: clip s, keep t
    const float* bsl = bsw + layer * ADIMV;
    const float* btl = btw + layer * ADIMV;
#pragma unroll
    for (int nt = 0; nt < 5; nt++)
#pragma unroll
        for (int e = 0; e < 4; e++) {
            int row = warp * 16 + g + ((e >= 2) ? 8 : 0);
            int col = nt * 8 + t4 * 2 + (e & 1);
            float v = a4[nt][e];
            if (col < ADIMV) {
                v += bsl[col];
                v = fminf(fmaxf(v, -2.0f), 2.0f);
            } else {
                v += btl[col - ADIMV];
            }
            st[row * DIMV + col] = v;
        }
    __syncthreads();

    // ---- per-row coupling epilogue ----
    if (tid < MTILE) {
        int r = tid;
        size_t gr = (size_t)rb + r;
        float ssum = 0.0f;
#pragma unroll
        for (int k = 0; k < ADIMV; k++) {
            float s = st[r * DIMV + k];
            ssum += s;
            float t = st[r * DIMV + ADIMV + k];
            float yb = zb[r * ADIMV + k] * __expf(s) + t;
            h1[r * ZROWSTR + sib[k]] = yb;
            h1[r * ZROWSTR + sia[k]] = za[r * ZASTR + k];
        }
        float ldv = (first ? 0.0f : g_ld[gr]) + ssum;
        if (last) ldfinal[gr] = ldv;
        else g_ld[gr] = ldv;
    }
    __syncthreads();
    // coalesced writeback of new z rows
    for (int i = tid; i < MTILE * DIMV; i += NTHR) {
        int r = i / DIMV, c = i - r * DIMV;
        zout[(size_t)(rb + r) * DIMV + c] = h1[r * ZROWSTR + c];
    }
}

extern "C" void kernel_launch(void* const* d_in, const int* in_sizes, int n_in,
                              void* d_out, int out_size) {
    const float* x   = (const float*)d_in[0];
    const float* ctx = (const float*)d_in[1];
    const float* te  = (const float*)d_in[2];
    const float* W1  = (const float*)d_in[3];
    const float* b1  = (const float*)d_in[4];
    const float* W2  = (const float*)d_in[5];
    const float* b2  = (const float*)d_in[6];
    const float* W3  = (const float*)d_in[7];
    const float* b3  = (const float*)d_in[8];
    const float* Ws  = (const float*)d_in[9];
    const float* bs  = (const float*)d_in[10];
    const float* Wt  = (const float*)d_in[11];
    const float* bt  = (const float*)d_in[12];
    const int* perm  = (const int*)d_in[13];
    const int* ia    = (const int*)d_in[14];
    const int* ib    = (const int*)d_in[15];

    float* outz  = (float*)d_out;
    float* outld = outz + (size_t)BTOT * DIMV;

    cudaFuncSetAttribute(flow_layer_kernel,
                         cudaFuncAttributeMaxDynamicSharedMemorySize, SMEM_BYTES);

    dim3 grid(BTOT / MTILE), blk(NTHR);
    for (int l = 0; l < L_LAYERS; l++) {
        flow_layer_kernel<<<grid, blk, SMEM_BYTES>>>(
            x, outz, outld, ctx, te, W1, b1, W2, b2, W3, b3, Ws, bs, Wt, bt,
            perm, ia, ib, l);
    }
    (void)in_sizes; (void)n_in; (void)out_size;
}

// round 2
// speedup vs baseline: 1.8897x; 1.8897x over previous
#include <cuda_runtime.h>

#define L_LAYERS 6
#define DIMV     40
#define HV       128
#define ADIMV    20
#define BTOT     131072
#define MTILE    64
#define NTHR     256
#define HSTR     132     // h row stride: 132 % 32 == 4 -> conflict-free frag LDS
#define ZASTR    28

// packed tf32 weight buffer offsets (floats, per layer)
#define PK_A   0          // W1 rows 0..19 (+4 zero rows), K=24,  N=128
#define PK_C   3072       // W1 rows 20..147,              K=128, N=128
#define PK_T   19456      // W1 rows 148..275,             K=128, N=128
#define PK_W2  35840      // K=128, N=128
#define PK_W3  52224      // K=128, N=128
#define PK_W4  68608      // [Ws|Wt|0pad], K=128, N=48
#define PK_L   74752

__device__ float g_wp[6 * PK_L];
__device__ float g_z[(size_t)BTOT * DIMV];
__device__ float g_ld[BTOT];

__device__ __forceinline__ unsigned f2tf(float x) {
    unsigned r;
    asm("cvt.rna.tf32.f32 %0, %1;" : "=r"(r) : "f"(x));
    return r;
}

__device__ __forceinline__ void mma8(float c[4], const unsigned a[4], const unsigned b[2]) {
    asm volatile(
        "mma.sync.aligned.m16n8k8.row.col.f32.tf32.tf32.f32 "
        "{%0,%1,%2,%3}, {%4,%5,%6,%7}, {%8,%9}, {%0,%1,%2,%3};\n"
        : "+f"(c[0]), "+f"(c[1]), "+f"(c[2]), "+f"(c[3])
        : "r"(a[0]), "r"(a[1]), "r"(a[2]), "r"(a[3]), "r"(b[0]), "r"(b[1]));
}

// ---------------------------------------------------------------------------
// prep: convert weights to tf32 and pack in B-fragment order:
//   idx(col,ks,t4,h) = ((col*KS+ks)*4+t4)*2+h ; src row = ks*8+t4+4h
// ---------------------------------------------------------------------------
__global__ void prep_kernel(const float* __restrict__ W1, const float* __restrict__ W2,
                            const float* __restrict__ W3, const float* __restrict__ Ws,
                            const float* __restrict__ Wt) {
    int i = blockIdx.x * blockDim.x + threadIdx.x;
    if (i >= 6 * PK_L) return;
    int layer = i / PK_L;
    int r = i - layer * PK_L;
    float v;
    if (r < PK_C) {                       // seg A: K=24, N=128
        int idx = r;
        int hh = idx & 1, t4 = (idx >> 1) & 3;
        int q = idx >> 3;
        int ks = q % 3, col = q / 3;
        int row = ks * 8 + t4 + 4 * hh;
        v = (row < ADIMV) ? W1[(size_t)layer * 276 * HV + row * HV + col] : 0.0f;
    } else if (r < PK_T) {                // seg C: K=128
        int idx = r - PK_C;
        int hh = idx & 1, t4 = (idx >> 1) & 3;
        int ks = (idx >> 3) & 15, col = idx >> 7;
        int row = ks * 8 + t4 + 4 * hh;
        v = W1[(size_t)layer * 276 * HV + (ADIMV + row) * HV + col];
    } else if (r < PK_W2) {               // seg T: K=128
        int idx = r - PK_T;
        int hh = idx & 1, t4 = (idx >> 1) & 3;
        int ks = (idx >> 3) & 15, col = idx >> 7;
        int row = ks * 8 + t4 + 4 * hh;
        v = W1[(size_t)layer * 276 * HV + (ADIMV + 128 + row) * HV + col];
    } else if (r < PK_W3) {
        int idx = r - PK_W2;
        int hh = idx & 1, t4 = (idx >> 1) & 3;
        int ks = (idx >> 3) & 15, col = idx >> 7;
        int row = ks * 8 + t4 + 4 * hh;
        v = W2[(size_t)layer * HV * HV + row * HV + col];
    } else if (r < PK_W4) {
        int idx = r - PK_W3;
        int hh = idx & 1, t4 = (idx >> 1) & 3;
        int ks = (idx >> 3) & 15, col = idx >> 7;
        int row = ks * 8 + t4 + 4 * hh;
        v = W3[(size_t)layer * HV * HV + row * HV + col];
    } else {                              // W4: K=128, N=48
        int idx = r - PK_W4;
        int hh = idx & 1, t4 = (idx >> 1) & 3;
        int ks = (idx >> 3) & 15, col = idx >> 7;
        int row = ks * 8 + t4 + 4 * hh;
        if (col < ADIMV)       v = Ws[(size_t)layer * HV * ADIMV + row * ADIMV + col];
        else if (col < DIMV)   v = Wt[(size_t)layer * HV * ADIMV + row * ADIMV + (col - ADIMV)];
        else                   v = 0.0f;
    }
    g_wp[i] = __uint_as_float(f2tf(v));
}

// ---------------------------------------------------------------------------
// GEMM helpers: warp tile = 16 rows x 64 cols (4m x 2n warps over 64x128)
// ---------------------------------------------------------------------------
__device__ __forceinline__ void gemm_smemA_128(float acc[8][4], const float* __restrict__ Ab,
                                               const float* __restrict__ Wp,
                                               int wm, int wn, int g, int t4) {
    const float2* bp = reinterpret_cast<const float2*>(Wp);
    const int colbase = wn * 64 + g;
#pragma unroll
    for (int ks = 0; ks < 16; ks++) {
        const float* ar = Ab + (wm * 16 + g) * HSTR + ks * 8 + t4;
        unsigned a[4];
        a[0] = __float_as_uint(ar[0]);
        a[1] = __float_as_uint(ar[8 * HSTR]);
        a[2] = __float_as_uint(ar[4]);
        a[3] = __float_as_uint(ar[8 * HSTR + 4]);
#pragma unroll
        for (int nt = 0; nt < 8; nt++) {
            float2 bv = bp[((colbase + nt * 8) * 16 + ks) * 4 + t4];
            unsigned b[2] = {__float_as_uint(bv.x), __float_as_uint(bv.y)};
            mma8(acc[nt], a, b);
        }
    }
}

__device__ __forceinline__ void gemm_gmemA_128(float acc[8][4], const float* __restrict__ Ag,
                                               const float* __restrict__ Wp,
                                               int wm, int wn, int g, int t4) {
    const float2* bp = reinterpret_cast<const float2*>(Wp);
    const int colbase = wn * 64 + g;
#pragma unroll
    for (int ks = 0; ks < 16; ks++) {
        const float* ar = Ag + (wm * 16 + g) * HV + ks * 8 + t4;
        unsigned a[4];
        a[0] = f2tf(__ldg(ar));
        a[1] = f2tf(__ldg(ar + 8 * HV));
        a[2] = f2tf(__ldg(ar + 4));
        a[3] = f2tf(__ldg(ar + 8 * HV + 4));
#pragma unroll
        for (int nt = 0; nt < 8; nt++) {
            float2 bv = bp[((colbase + nt * 8) * 16 + ks) * 4 + t4];
            unsigned b[2] = {__float_as_uint(bv.x), __float_as_uint(bv.y)};
            mma8(acc[nt], a, b);
        }
    }
}

__device__ __forceinline__ void epi_silu(float acc[8][4], const float* __restrict__ bias,
                                         float* __restrict__ h, int wm, int wn, int g, int t4) {
#pragma unroll
    for (int nt = 0; nt < 8; nt++)
#pragma unroll
        for (int e = 0; e < 4; e++) {
            int row = wm * 16 + g + ((e >= 2) ? 8 : 0);
            int col = wn * 64 + nt * 8 + t4 * 2 + (e & 1);
            float v = acc[nt][e] + __ldg(bias + col);
            v = __fdividef(v, 1.0f + __expf(-v));
            h[row * HSTR + col] = __uint_as_float(f2tf(v));
        }
}

// ---------------------------------------------------------------------------
__global__ void __launch_bounds__(NTHR, 3)
flow_layer_kernel(const float* __restrict__ xin, float* __restrict__ zfinal,
                  float* __restrict__ ldfinal,
                  const float* __restrict__ ctx, const float* __restrict__ te,
                  const float* __restrict__ b1, const float* __restrict__ b2,
                  const float* __restrict__ b3, const float* __restrict__ bsw,
                  const float* __restrict__ btw,
                  const int* __restrict__ perm, const int* __restrict__ idxa,
                  const int* __restrict__ idxb, int layer) {
    __shared__ float h_s[MTILE * HSTR];
    __shared__ float za_s[MTILE * ZASTR];
    __shared__ float zb_s[MTILE * ADIMV];
    __shared__ int sia[ADIMV], sib[ADIMV], sga[ADIMV], sgb[ADIMV];

    const int tid = threadIdx.x;
    const int warp = tid >> 5, lane = tid & 31;
    const int g = lane >> 2, t4 = lane & 3;
    const int wm = warp >> 1, wn = warp & 1;
    const int rb = blockIdx.x * MTILE;
    const bool first = (layer == 0), last = (layer == L_LAYERS - 1);
    const float* zin = first ? xin : g_z;
    float* zout = last ? zfinal : g_z;
    const float* wl = g_wp + layer * PK_L;

    if (tid < ADIMV) {
        int v = idxa[layer * ADIMV + tid];
        sia[tid] = v;
        sga[tid] = perm[layer * DIMV + v];
    } else if (tid < 2 * ADIMV) {
        int k = tid - ADIMV;
        int v = idxb[layer * ADIMV + k];
        sib[k] = v;
        sgb[k] = perm[layer * DIMV + v];
    }
    // coalesced z rows -> h scratch
    for (int i = tid; i < MTILE * DIMV; i += NTHR) {
        int r = i / DIMV, c = i - r * DIMV;
        h_s[r * HSTR + c] = zin[(size_t)(rb + r) * DIMV + c];
    }
    __syncthreads();
    // gather permuted halves (za raw fp32; zb raw fp32)
    for (int i = tid; i < MTILE * ADIMV; i += NTHR) {
        int r = i / ADIMV, k = i - r * ADIMV;
        za_s[r * ZASTR + k] = h_s[r * HSTR + sga[k]];
        zb_s[r * ADIMV + k] = h_s[r * HSTR + sgb[k]];
    }
    for (int i = tid; i < MTILE * 4; i += NTHR) {
        int r = i >> 2, c = i & 3;
        za_s[r * ZASTR + ADIMV + c] = 0.0f;
    }
    __syncthreads();

    float acc[8][4];
#pragma unroll
    for (int nt = 0; nt < 8; nt++)
#pragma unroll
        for (int e = 0; e < 4; e++) acc[nt][e] = 0.0f;

    // ---- GEMM1: za seg (K=24, A in smem, cvt at use) ----
    {
        const float2* bp = reinterpret_cast<const float2*>(wl + PK_A);
        const int colbase = wn * 64 + g;
#pragma unroll
        for (int ks = 0; ks < 3; ks++) {
            const float* ar = za_s + (wm * 16 + g) * ZASTR + ks * 8 + t4;
            unsigned a[4];
            a[0] = f2tf(ar[0]);
            a[1] = f2tf(ar[8 * ZASTR]);
            a[2] = f2tf(ar[4]);
            a[3] = f2tf(ar[8 * ZASTR + 4]);
#pragma unroll
            for (int nt = 0; nt < 8; nt++) {
                float2 bv = bp[((colbase + nt * 8) * 3 + ks) * 4 + t4];
                unsigned b[2] = {__float_as_uint(bv.x), __float_as_uint(bv.y)};
                mma8(acc[nt], a, b);
            }
        }
    }
    // ---- GEMM1: ctx / te segs (A direct from gmem) ----
    gemm_gmemA_128(acc, ctx + (size_t)rb * HV, wl + PK_C, wm, wn, g, t4);
    gemm_gmemA_128(acc, te + (size_t)rb * HV, wl + PK_T, wm, wn, g, t4);
    epi_silu(acc, b1 + layer * HV, h_s, wm, wn, g, t4);
    __syncthreads();

    // ---- GEMM2 (in-place h) ----
#pragma unroll
    for (int nt = 0; nt < 8; nt++)
#pragma unroll
        for (int e = 0; e < 4; e++) acc[nt][e] = 0.0f;
    gemm_smemA_128(acc, h_s, wl + PK_W2, wm, wn, g, t4);
    __syncthreads();
    epi_silu(acc, b2 + layer * HV, h_s, wm, wn, g, t4);
    __syncthreads();

    // ---- GEMM3 (in-place h) ----
#pragma unroll
    for (int nt = 0; nt < 8; nt++)
#pragma unroll
        for (int e = 0; e < 4; e++) acc[nt][e] = 0.0f;
    gemm_smemA_128(acc, h_s, wl + PK_W3, wm, wn, g, t4);
    __syncthreads();
    epi_silu(acc, b3 + layer * HV, h_s, wm, wn, g, t4);
    __syncthreads();

    // ---- GEMM4: h @ [Ws|Wt] (N=48 padded), warp tile 16x24 ----
    float a4[3][4];
#pragma unroll
    for (int nt = 0; nt < 3; nt++)
#pragma unroll
        for (int e = 0; e < 4; e++) a4[nt][e] = 0.0f;
    {
        const float2* bp = reinterpret_cast<const float2*>(wl + PK_W4);
        const int colbase = wn * 24 + g;
#pragma unroll
        for (int ks = 0; ks < 16; ks++) {
            const float* ar = h_s + (wm * 16 + g) * HSTR + ks * 8 + t4;
            unsigned a[4];
            a[0] = __float_as_uint(ar[0]);
            a[1] = __float_as_uint(ar[8 * HSTR]);
            a[2] = __float_as_uint(ar[4]);
            a[3] = __float_as_uint(ar[8 * HSTR + 4]);
#pragma unroll
            for (int nt = 0; nt < 3; nt++) {
                float2 bv = bp[((colbase + nt * 8) * 16 + ks) * 4 + t4];
                unsigned b[2] = {__float_as_uint(bv.x), __float_as_uint(bv.y)};
                mma8(a4[nt], a, b);
            }
        }
    }
    __syncthreads();
    // epilogue4: write s (clipped, cols 0..19) and t (cols 20..39) into h cols 0..39
    {
        const float* bsl = bsw + layer * ADIMV;
        const float* btl = btw + layer * ADIMV;
#pragma unroll
        for (int nt = 0; nt < 3; nt++)
#pragma unroll
            for (int e = 0; e < 4; e++) {
                int row = wm * 16 + g + ((e >= 2) ? 8 : 0);
                int col = wn * 24 + nt * 8 + t4 * 2 + (e & 1);
                if (col < DIMV) {
                    float v = a4[nt][e];
                    if (col < ADIMV) {
                        v += __ldg(bsl + col);
                        v = fminf(fmaxf(v, -2.0f), 2.0f);
                    } else {
                        v += __ldg(btl + col - ADIMV);
                    }
                    h_s[row * HSTR + col] = v;
                }
            }
    }
    __syncthreads();

    // ---- coupling: 4 threads per row, 5 k each; z_out in h cols 64..103 ----
    {
        int r = tid >> 2, q = tid & 3;
        float ssum = 0.0f;
#pragma unroll
        for (int j = 0; j < 5; j++) {
            int k = q * 5 + j;
            float s = h_s[r * HSTR + k];
            float t = h_s[r * HSTR + ADIMV + k];
            ssum += s;
            float yb = zb_s[r * ADIMV + k] * __expf(s) + t;
            h_s[r * HSTR + 64 + sib[k]] = yb;
            h_s[r * HSTR + 64 + sia[k]] = za_s[r * ZASTR + k];
        }
        ssum += __shfl_xor_sync(0xffffffffu, ssum, 1);
        ssum += __shfl_xor_sync(0xffffffffu, ssum, 2);
        if (q == 0) {
            size_t gr = (size_t)rb + r;
            float ldv = (first ? 0.0f : g_ld[gr]) + ssum;
            if (last) ldfinal[gr] = ldv;
            else g_ld[gr] = ldv;
        }
    }
    __syncthreads();
    // coalesced writeback
    for (int i = tid; i < MTILE * DIMV; i += NTHR) {
        int r = i / DIMV, c = i - r * DIMV;
        zout[(size_t)(rb + r) * DIMV + c] = h_s[r * HSTR + 64 + c];
    }
}

extern "C" void kernel_launch(void* const* d_in, const int* in_sizes, int n_in,
                              void* d_out, int out_size) {
    const float* x   = (const float*)d_in[0];
    const float* ctx = (const float*)d_in[1];
    const float* te  = (const float*)d_in[2];
    const float* W1  = (const float*)d_in[3];
    const float* b1  = (const float*)d_in[4];
    const float* W2  = (const float*)d_in[5];
    const float* b2  = (const float*)d_in[6];
    const float* W3  = (const float*)d_in[7];
    const float* b3  = (const float*)d_in[8];
    const float* Ws  = (const float*)d_in[9];
    const float* bs  = (const float*)d_in[10];
    const float* Wt  = (const float*)d_in[11];
    const float* bt  = (const float*)d_in[12];
    const int* perm  = (const int*)d_in[13];
    const int* ia    = (const int*)d_in[14];
    const int* ib    = (const int*)d_in[15];

    float* outz  = (float*)d_out;
    float* outld = outz + (size_t)BTOT * DIMV;

    prep_kernel<<<(6 * PK_L + 255) / 256, 256>>>(W1, W2, W3, Ws, Wt);

    dim3 grid(BTOT / MTILE), blk(NTHR);
    for (int l = 0; l < L_LAYERS; l++) {
        flow_layer_kernel<<<grid, blk>>>(
            x, outz, outld, ctx, te, b1, b2, b3, bs, bt, perm, ia, ib, l);
    }
    (void)in_sizes; (void)n_in; (void)out_size;
}

// round 3
// speedup vs baseline: 4.9607x; 2.6252x over previous
#include <cuda_runtime.h>

#define L_LAYERS 6
#define DIMV     40
#define HV       128
#define ADIMV    20
#define BTOT     131072
#define MTILE    64
#define NTHR     256
#define HSTR     132     // h row stride: 132 % 32 == 4 -> conflict-free frag LDS
#define ZASTR    28

// packed tf32 weight buffer offsets (floats, per layer)
// float4-block layout: blk=(ks*NTP+ntp), float4 per lane: {nt0h0,nt0h1,nt1h0,nt1h1}
#define PK_A   0          // W1 rows 0..19(+4 pad), KS=3,  NTP=8
#define PK_C   3072       // W1 rows 20..147,       KS=16, NTP=8
#define PK_T   19456      // W1 rows 148..275
#define PK_W2  35840
#define PK_W3  52224
#define PK_W4  68608      // [Ws|Wt|0pad], KS=16, NT=6 (float2 layout)
#define PK_L   74752

__device__ float g_wp[6 * PK_L];

__device__ __forceinline__ unsigned f2tf(float x) {
    unsigned r;
    asm("cvt.rna.tf32.f32 %0, %1;" : "=r"(r) : "f"(x));
    return r;
}

__device__ __forceinline__ void mma8(float c[4], const unsigned a[4], const unsigned b[2]) {
    asm volatile(
        "mma.sync.aligned.m16n8k8.row.col.f32.tf32.tf32.f32 "
        "{%0,%1,%2,%3}, {%4,%5,%6,%7}, {%8,%9}, {%0,%1,%2,%3};\n"
        : "+f"(c[0]), "+f"(c[1]), "+f"(c[2]), "+f"(c[3])
        : "r"(a[0]), "r"(a[1]), "r"(a[2]), "r"(a[3]), "r"(b[0]), "r"(b[1]));
}

// ---------------------------------------------------------------------------
// prep: tf32-convert weights, pack fragment-contiguous.
// float4 regions: idx -> comp=idx&3 (ntl=comp>>1, h=comp&1); lane=(idx>>2)&31;
//   blk=idx>>7; ntp=blk&7; ks=blk>>3; row=ks*8+(lane&3)+4*h;
//   col=(ntp*2+ntl)*8+(lane>>2)
// ---------------------------------------------------------------------------
__global__ void prep_kernel(const float* __restrict__ W1, const float* __restrict__ W2,
                            const float* __restrict__ W3, const float* __restrict__ Ws,
                            const float* __restrict__ Wt) {
    int i = blockIdx.x * blockDim.x + threadIdx.x;
    if (i >= 6 * PK_L) return;
    int layer = i / PK_L;
    int r = i - layer * PK_L;
    float v;
    if (r < PK_W4) {
        int idx, seg;
        if (r < PK_C)      { idx = r;         seg = 0; }
        else if (r < PK_T) { idx = r - PK_C;  seg = 1; }
        else if (r < PK_W2){ idx = r - PK_T;  seg = 2; }
        else if (r < PK_W3){ idx = r - PK_W2; seg = 3; }
        else               { idx = r - PK_W3; seg = 4; }
        int comp = idx & 3, ntl = comp >> 1, hh = comp & 1;
        int lane = (idx >> 2) & 31, t4 = lane & 3, g = lane >> 2;
        int blk = idx >> 7, ntp = blk & 7, ks = blk >> 3;
        int row = ks * 8 + t4 + 4 * hh;
        int col = (ntp * 2 + ntl) * 8 + g;
        if (seg == 0)      v = (row < ADIMV) ? W1[(size_t)layer * 276 * HV + row * HV + col] : 0.0f;
        else if (seg == 1) v = W1[(size_t)layer * 276 * HV + (ADIMV + row) * HV + col];
        else if (seg == 2) v = W1[(size_t)layer * 276 * HV + (ADIMV + 128 + row) * HV + col];
        else if (seg == 3) v = W2[(size_t)layer * HV * HV + row * HV + col];
        else               v = W3[(size_t)layer * HV * HV + row * HV + col];
        g_wp[i] = __uint_as_float(f2tf(v));
    } else {
        // W4 float2 layout: idx -> h=idx&1; lane=(idx>>1)&31; blk=idx>>6; nt=blk%6; ks=blk/6
        int idx = r - PK_W4;
        int hh = idx & 1;
        int lane = (idx >> 1) & 31, t4 = lane & 3, g = lane >> 2;
        int blk = idx >> 6, nt = blk % 6, ks = blk / 6;
        int row = ks * 8 + t4 + 4 * hh;
        int col = nt * 8 + g;
        if (col < ADIMV)     v = Ws[(size_t)layer * HV * ADIMV + row * ADIMV + col];
        else if (col < DIMV) v = Wt[(size_t)layer * HV * ADIMV + row * ADIMV + (col - ADIMV)];
        else                 v = 0.0f;
        g_wp[i] = __uint_as_float(f2tf(v));
    }
}

// ---------------------------------------------------------------------------
// warp tile 16x64 (4m x 2n over 64x128); A pre-tf32 in smem, B packed float4
// ---------------------------------------------------------------------------
__device__ __forceinline__ void gemm128(float acc[8][4], const float* __restrict__ Ab,
                                        const float* __restrict__ Wp,
                                        int wm, int wn, int lane, int g, int t4) {
    const float4* bp = reinterpret_cast<const float4*>(Wp);
#pragma unroll
    for (int ks = 0; ks < 16; ks++) {
        const float* ar = Ab + (wm * 16 + g) * HSTR + ks * 8 + t4;
        unsigned a[4];
        a[0] = __float_as_uint(ar[0]);
        a[1] = __float_as_uint(ar[8 * HSTR]);
        a[2] = __float_as_uint(ar[4]);
        a[3] = __float_as_uint(ar[8 * HSTR + 4]);
        const float4* bb = bp + (ks * 8 + wn * 4) * 32 + lane;
#pragma unroll
        for (int ntp = 0; ntp < 4; ntp++) {
            float4 bv = __ldg(bb + ntp * 32);
            unsigned b0[2] = {__float_as_uint(bv.x), __float_as_uint(bv.y)};
            unsigned b1[2] = {__float_as_uint(bv.z), __float_as_uint(bv.w)};
            mma8(acc[2 * ntp], a, b0);
            mma8(acc[2 * ntp + 1], a, b1);
        }
    }
}

__device__ __forceinline__ void epi_silu(float acc[8][4], const float* __restrict__ bias,
                                         float* __restrict__ h, int wm, int wn, int g, int t4) {
#pragma unroll
    for (int nt = 0; nt < 8; nt++)
#pragma unroll
        for (int e = 0; e < 4; e++) {
            int row = wm * 16 + g + ((e >= 2) ? 8 : 0);
            int col = wn * 64 + nt * 8 + t4 * 2 + (e & 1);
            float v = acc[nt][e] + __ldg(bias + col);
            v = __fdividef(v, 1.0f + __expf(-v));
            h[row * HSTR + col] = __uint_as_float(f2tf(v));
        }
}

__device__ __forceinline__ void stage_tf32(float* __restrict__ h, const float* __restrict__ src,
                                           int rb, int tid) {
#pragma unroll
    for (int i = tid; i < MTILE * 32; i += NTHR) {
        int r = i >> 5, c4 = (i & 31) << 2;
        float4 v = *reinterpret_cast<const float4*>(src + (size_t)(rb + r) * HV + c4);
        float4 w;
        w.x = __uint_as_float(f2tf(v.x));
        w.y = __uint_as_float(f2tf(v.y));
        w.z = __uint_as_float(f2tf(v.z));
        w.w = __uint_as_float(f2tf(v.w));
        *reinterpret_cast<float4*>(h + r * HSTR + c4) = w;
    }
}

// ---------------------------------------------------------------------------
__global__ void __launch_bounds__(NTHR, 3)
flow_fused_kernel(const float* __restrict__ xin, float* __restrict__ zfinal,
                  float* __restrict__ ldfinal,
                  const float* __restrict__ ctx, const float* __restrict__ te,
                  const float* __restrict__ b1, const float* __restrict__ b2,
                  const float* __restrict__ b3, const float* __restrict__ bsw,
                  const float* __restrict__ btw,
                  const int* __restrict__ perm, const int* __restrict__ idxa,
                  const int* __restrict__ idxb) {
    __shared__ float h_s[MTILE * HSTR];
    __shared__ float za_s[MTILE * ZASTR];
    __shared__ float zb_s[MTILE * ADIMV];
    __shared__ int sia[ADIMV], sib[ADIMV], sga[ADIMV], sgb[ADIMV];

    const int tid = threadIdx.x;
    const int warp = tid >> 5, lane = tid & 31;
    const int g = lane >> 2, t4 = lane & 3;
    const int wm = warp >> 1, wn = warp & 1;
    const int rb = blockIdx.x * MTILE;

    // initial z = x into h cols 64..103
    for (int i = tid; i < MTILE * DIMV; i += NTHR) {
        int r = i / DIMV, c = i - r * DIMV;
        h_s[r * HSTR + 64 + c] = xin[(size_t)(rb + r) * DIMV + c];
    }

    float ldacc = 0.0f;

    for (int layer = 0; layer < L_LAYERS; layer++) {
        const float* wl = g_wp + layer * PK_L;

        if (tid < ADIMV) {
            int v = idxa[layer * ADIMV + tid];
            sia[tid] = v;
            sga[tid] = perm[layer * DIMV + v];
        } else if (tid < 2 * ADIMV) {
            int k = tid - ADIMV;
            int v = idxb[layer * ADIMV + k];
            sib[k] = v;
            sgb[k] = perm[layer * DIMV + v];
        }
        __syncthreads();
        // gather permuted halves from z region
        for (int i = tid; i < MTILE * ADIMV; i += NTHR) {
            int r = i / ADIMV, k = i - r * ADIMV;
            za_s[r * ZASTR + k] = h_s[r * HSTR + 64 + sga[k]];
            zb_s[r * ADIMV + k] = h_s[r * HSTR + 64 + sgb[k]];
        }
        for (int i = tid; i < MTILE * 4; i += NTHR) {
            int r = i >> 2, c = i & 3;
            za_s[r * ZASTR + ADIMV + c] = 0.0f;
        }
        __syncthreads();

        float acc[8][4];
#pragma unroll
        for (int nt = 0; nt < 8; nt++)
#pragma unroll
            for (int e = 0; e < 4; e++) acc[nt][e] = 0.0f;

        // GEMM1 seg z_a (K=24, cvt at use from za_s)
        {
            const float4* bp = reinterpret_cast<const float4*>(wl + PK_A);
#pragma unroll
            for (int ks = 0; ks < 3; ks++) {
                const float* ar = za_s + (wm * 16 + g) * ZASTR + ks * 8 + t4;
                unsigned a[4];
                a[0] = f2tf(ar[0]);
                a[1] = f2tf(ar[8 * ZASTR]);
                a[2] = f2tf(ar[4]);
                a[3] = f2tf(ar[8 * ZASTR + 4]);
                const float4* bb = bp + (ks * 8 + wn * 4) * 32 + lane;
#pragma unroll
                for (int ntp = 0; ntp < 4; ntp++) {
                    float4 bv = __ldg(bb + ntp * 32);
                    unsigned b0[2] = {__float_as_uint(bv.x), __float_as_uint(bv.y)};
                    unsigned b1[2] = {__float_as_uint(bv.z), __float_as_uint(bv.w)};
                    mma8(acc[2 * ntp], a, b0);
                    mma8(acc[2 * ntp + 1], a, b1);
                }
            }
        }
        // GEMM1 seg ctx (staged via smem)
        stage_tf32(h_s, ctx, rb, tid);
        __syncthreads();
        gemm128(acc, h_s, wl + PK_C, wm, wn, lane, g, t4);
        __syncthreads();
        // GEMM1 seg te
        stage_tf32(h_s, te, rb, tid);
        __syncthreads();
        gemm128(acc, h_s, wl + PK_T, wm, wn, lane, g, t4);
        __syncthreads();
        epi_silu(acc, b1 + layer * HV, h_s, wm, wn, g, t4);
        __syncthreads();

        // GEMM2
#pragma unroll
        for (int nt = 0; nt < 8; nt++)
#pragma unroll
            for (int e = 0; e < 4; e++) acc[nt][e] = 0.0f;
        gemm128(acc, h_s, wl + PK_W2, wm, wn, lane, g, t4);
        __syncthreads();
        epi_silu(acc, b2 + layer * HV, h_s, wm, wn, g, t4);
        __syncthreads();

        // GEMM3
#pragma unroll
        for (int nt = 0; nt < 8; nt++)
#pragma unroll
            for (int e = 0; e < 4; e++) acc[nt][e] = 0.0f;
        gemm128(acc, h_s, wl + PK_W3, wm, wn, lane, g, t4);
        __syncthreads();
        epi_silu(acc, b3 + layer * HV, h_s, wm, wn, g, t4);
        __syncthreads();

        // GEMM4: h @ [Ws|Wt] (N=48), warp tile 16x24
        float a4[3][4];
#pragma unroll
        for (int nt = 0; nt < 3; nt++)
#pragma unroll
            for (int e = 0; e < 4; e++) a4[nt][e] = 0.0f;
        {
            const float2* bp2 = reinterpret_cast<const float2*>(wl + PK_W4);
#pragma unroll
            for (int ks = 0; ks < 16; ks++) {
                const float* ar = h_s + (wm * 16 + g) * HSTR + ks * 8 + t4;
                unsigned a[4];
                a[0] = __float_as_uint(ar[0]);
                a[1] = __float_as_uint(ar[8 * HSTR]);
                a[2] = __float_as_uint(ar[4]);
                a[3] = __float_as_uint(ar[8 * HSTR + 4]);
#pragma unroll
                for (int nt = 0; nt < 3; nt++) {
                    float2 bv = __ldg(bp2 + (ks * 6 + wn * 3 + nt) * 32 + lane);
                    unsigned b[2] = {__float_as_uint(bv.x), __float_as_uint(bv.y)};
                    mma8(a4[nt], a, b);
                }
            }
        }
        __syncthreads();
        // epilogue4 -> h cols 0..39 (s clipped | t)
        {
            const float* bsl = bsw + layer * ADIMV;
            const float* btl = btw + layer * ADIMV;
#pragma unroll
            for (int nt = 0; nt < 3; nt++)
#pragma unroll
                for (int e = 0; e < 4; e++) {
                    int row = wm * 16 + g + ((e >= 2) ? 8 : 0);
                    int col = wn * 24 + nt * 8 + t4 * 2 + (e & 1);
                    if (col < DIMV) {
                        float v = a4[nt][e];
                        if (col < ADIMV) {
                            v += __ldg(bsl + col);
                            v = fminf(fmaxf(v, -2.0f), 2.0f);
                        } else {
                            v += __ldg(btl + col - ADIMV);
                        }
                        h_s[row * HSTR + col] = v;
                    }
                }
        }
        __syncthreads();

        // coupling: 4 threads/row; write new z into h cols 64..103
        {
            int r = tid >> 2, q = tid & 3;
            float ssum = 0.0f;
#pragma unroll
            for (int j = 0; j < 5; j++) {
                int k = q * 5 + j;
                float s = h_s[r * HSTR + k];
                float t = h_s[r * HSTR + ADIMV + k];
                ssum += s;
                float yb = zb_s[r * ADIMV + k] * __expf(s) + t;
                h_s[r * HSTR + 64 + sib[k]] = yb;
                h_s[r * HSTR + 64 + sia[k]] = za_s[r * ZASTR + k];
            }
            ssum += __shfl_xor_sync(0xffffffffu, ssum, 1);
            ssum += __shfl_xor_sync(0xffffffffu, ssum, 2);
            ldacc += ssum;
        }
        __syncthreads();
    }

    // final writeback
    for (int i = tid; i < MTILE * DIMV; i += NTHR) {
        int r = i / DIMV, c = i - r * DIMV;
        zfinal[(size_t)(rb + r) * DIMV + c] = h_s[r * HSTR + 64 + c];
    }
    if ((tid & 3) == 0) {
        int r = tid >> 2;
        ldfinal[(size_t)rb + r] = ldacc;
    }
}

extern "C" void kernel_launch(void* const* d_in, const int* in_sizes, int n_in,
                              void* d_out, int out_size) {
    const float* x   = (const float*)d_in[0];
    const float* ctx = (const float*)d_in[1];
    const float* te  = (const float*)d_in[2];
    const float* W1  = (const float*)d_in[3];
    const float* b1  = (const float*)d_in[4];
    const float* W2  = (const float*)d_in[5];
    const float* b2  = (const float*)d_in[6];
    const float* W3  = (const float*)d_in[7];
    const float* b3  = (const float*)d_in[8];
    const float* Ws  = (const float*)d_in[9];
    const float* bs  = (const float*)d_in[10];
    const float* Wt  = (const float*)d_in[11];
    const float* bt  = (const float*)d_in[12];
    const int* perm  = (const int*)d_in[13];
    const int* ia    = (const int*)d_in[14];
    const int* ib    = (const int*)d_in[15];

    float* outz  = (float*)d_out;
    float* outld = outz + (size_t)BTOT * DIMV;

    prep_kernel<<<(6 * PK_L + 255) / 256, 256>>>(W1, W2, W3, Ws, Wt);

    dim3 grid(BTOT / MTILE), blk(NTHR);
    flow_fused_kernel<<<grid, blk>>>(
        x, outz, outld, ctx, te, b1, b2, b3, bs, bt, perm, ia, ib);
    (void)in_sizes; (void)n_in; (void)out_size;
}